// round 1
// baseline (speedup 1.0000x reference)
#include <cuda_runtime.h>
#include <cstdint>

// GridEncoder (instant-ngp style), D=3, L=16, C=2, H=16, PLS=2, log2_hashmap=19,
// align_corners=false. All per-level metadata is compile-time constant.

#define NLEV 16
#define PRIME1 2654435761u
#define PRIME2 805459861u
#define HASH_MASK 0x7FFFFu   // size = 2^19 for hashed levels

// Per-level offsets into the embedding table (rows of 2 floats).
__constant__ uint32_t c_off[NLEV] = {
    0u, 4920u, 40864u, 315496u,
    839784u, 1364072u, 1888360u, 2412648u,
    2936936u, 3461224u, 3985512u, 4509800u,
    5034088u, 5558376u, 6082664u, 6606952u
};
// scale = 16*2^l - 1  (exactly representable in fp32)
__constant__ float c_scale[NLEV] = {
    15.f, 31.f, 63.f, 127.f, 255.f, 511.f, 1023.f, 2047.f,
    4095.f, 8191.f, 16383.f, 32767.f, 65535.f, 131071.f, 262143.f, 524287.f
};
// dense levels 0..2: base = res+1
__constant__ uint32_t c_base[3] = {17u, 33u, 65u};

__global__ void __launch_bounds__(256)
grid_encode_kernel(const float* __restrict__ in,
                   const float2* __restrict__ emb,
                   float2* __restrict__ out,
                   int B)
{
    int t = blockIdx.x * blockDim.x + threadIdx.x;
    int p = t >> 4;           // point index
    int l = t & 15;           // level index
    if (p >= B) return;

    // map inputs from [-1,1] to [0,1]
    float x = (in[p * 3 + 0] + 1.0f) * 0.5f;
    float y = (in[p * 3 + 1] + 1.0f) * 0.5f;
    float z = (in[p * 3 + 2] + 1.0f) * 0.5f;

    float scale = c_scale[l];
    float px = fmaf(x, scale, 0.5f);
    float py = fmaf(y, scale, 0.5f);
    float pz = fmaf(z, scale, 0.5f);

    float fx = floorf(px), fy = floorf(py), fz = floorf(pz);
    uint32_t gx = (uint32_t)fx, gy = (uint32_t)fy, gz = (uint32_t)fz;
    float rx = px - fx, ry = py - fy, rz = pz - fz;

    uint32_t off = c_off[l];

    uint32_t id0, id1, id2, id3, id4, id5, id6, id7;
    if (l >= 3) {
        // hashed: idx = (cx*1 ^ cy*P1 ^ cz*P2) & MASK
        uint32_t x0 = gx,              x1 = gx + 1u;
        uint32_t y0 = gy * PRIME1,     y1 = (gy + 1u) * PRIME1;
        uint32_t z0 = gz * PRIME2,     z1 = (gz + 1u) * PRIME2;
        id0 = ((x0 ^ y0 ^ z0) & HASH_MASK) + off;
        id1 = ((x1 ^ y0 ^ z0) & HASH_MASK) + off;
        id2 = ((x0 ^ y1 ^ z0) & HASH_MASK) + off;
        id3 = ((x1 ^ y1 ^ z0) & HASH_MASK) + off;
        id4 = ((x0 ^ y0 ^ z1) & HASH_MASK) + off;
        id5 = ((x1 ^ y0 ^ z1) & HASH_MASK) + off;
        id6 = ((x0 ^ y1 ^ z1) & HASH_MASK) + off;
        id7 = ((x1 ^ y1 ^ z1) & HASH_MASK) + off;
    } else {
        // dense: idx = cx + cy*base + cz*base^2  (always < padded size, no mod)
        uint32_t base = c_base[l];
        uint32_t b2 = base * base;
        uint32_t x0 = gx,        x1 = gx + 1u;
        uint32_t y0 = gy * base, y1 = y0 + base;
        uint32_t z0 = gz * b2,   z1 = z0 + b2;
        id0 = x0 + y0 + z0 + off;
        id1 = x1 + y0 + z0 + off;
        id2 = x0 + y1 + z0 + off;
        id3 = x1 + y1 + z0 + off;
        id4 = x0 + y0 + z1 + off;
        id5 = x1 + y0 + z1 + off;
        id6 = x0 + y1 + z1 + off;
        id7 = x1 + y1 + z1 + off;
    }

    // 8 independent gathers — issue all before consuming
    float2 e0 = __ldg(&emb[id0]);
    float2 e1 = __ldg(&emb[id1]);
    float2 e2 = __ldg(&emb[id2]);
    float2 e3 = __ldg(&emb[id3]);
    float2 e4 = __ldg(&emb[id4]);
    float2 e5 = __ldg(&emb[id5]);
    float2 e6 = __ldg(&emb[id6]);
    float2 e7 = __ldg(&emb[id7]);

    float wx0 = 1.0f - rx, wx1 = rx;
    float wy0 = 1.0f - ry, wy1 = ry;
    float wz0 = 1.0f - rz, wz1 = rz;

    float w0 = wx0 * wy0 * wz0;
    float w1 = wx1 * wy0 * wz0;
    float w2 = wx0 * wy1 * wz0;
    float w3 = wx1 * wy1 * wz0;
    float w4 = wx0 * wy0 * wz1;
    float w5 = wx1 * wy0 * wz1;
    float w6 = wx0 * wy1 * wz1;
    float w7 = wx1 * wy1 * wz1;

    float a0 = w0 * e0.x;           float a1 = w0 * e0.y;
    a0 = fmaf(w1, e1.x, a0);        a1 = fmaf(w1, e1.y, a1);
    a0 = fmaf(w2, e2.x, a0);        a1 = fmaf(w2, e2.y, a1);
    a0 = fmaf(w3, e3.x, a0);        a1 = fmaf(w3, e3.y, a1);
    a0 = fmaf(w4, e4.x, a0);        a1 = fmaf(w4, e4.y, a1);
    a0 = fmaf(w5, e5.x, a0);        a1 = fmaf(w5, e5.y, a1);
    a0 = fmaf(w6, e6.x, a0);        a1 = fmaf(w6, e6.y, a1);
    a0 = fmaf(w7, e7.x, a0);        a1 = fmaf(w7, e7.y, a1);

    // out[p][2l .. 2l+1]; warp = 2 points x 16 levels -> coalesced 2x128B rows
    out[p * 16 + l] = make_float2(a0, a1);
}

extern "C" void kernel_launch(void* const* d_in, const int* in_sizes, int n_in,
                              void* d_out, int out_size) {
    const float*  inputs = (const float*)d_in[0];       // [B, 3]
    const float2* emb    = (const float2*)d_in[1];      // [TOTAL_PARAMS, 2] as float2
    float2*       out    = (float2*)d_out;              // [B, 16] of float2

    int B = in_sizes[0] / 3;
    int threads = 256;
    long long total = (long long)B * 16;
    int blocks = (int)((total + threads - 1) / threads);
    grid_encode_kernel<<<blocks, threads>>>(inputs, emb, out, B);
}

// round 2
// speedup vs baseline: 1.1608x; 1.1608x over previous
#include <cuda_runtime.h>
#include <cstdint>

// GridEncoder (instant-ngp style), D=3, L=16, C=2, H=16, PLS=2, log2_hashmap=19,
// align_corners=false. All per-level metadata is compile-time constant.
//
// R2: fuse x-adjacent corner pairs into one 16B gather when (idA ^ idB)==1
// (dense: idA even; hashed: gx even) -> ~25% fewer L1tex wavefronts.

#define NLEV 16
#define PRIME1 2654435761u
#define PRIME2 805459861u
#define HASH_MASK 0x7FFFFu   // size = 2^19 for hashed levels

__constant__ uint32_t c_off[NLEV] = {
    0u, 4920u, 40864u, 315496u,
    839784u, 1364072u, 1888360u, 2412648u,
    2936936u, 3461224u, 3985512u, 4509800u,
    5034088u, 5558376u, 6082664u, 6606952u
};
__constant__ float c_scale[NLEV] = {
    15.f, 31.f, 63.f, 127.f, 255.f, 511.f, 1023.f, 2047.f,
    4095.f, 8191.f, 16383.f, 32767.f, 65535.f, 131071.f, 262143.f, 524287.f
};
__constant__ uint32_t c_base[3] = {17u, 33u, 65u};

// Load the embeddings for an x-adjacent corner pair. If the two indices differ
// only in bit 0, the pair {id&~1, id|1} is one 16B-aligned float4 -> 1 sector.
__device__ __forceinline__ void load_pair(const float2* __restrict__ e2,
                                          const float4* __restrict__ e4,
                                          uint32_t iA, uint32_t iB,
                                          float2& ea, float2& eb)
{
    if ((iA ^ iB) == 1u) {
        float4 q = __ldg(&e4[iA >> 1]);
        if (iA & 1u) {
            ea = make_float2(q.z, q.w);
            eb = make_float2(q.x, q.y);
        } else {
            ea = make_float2(q.x, q.y);
            eb = make_float2(q.z, q.w);
        }
    } else {
        ea = __ldg(&e2[iA]);
        eb = __ldg(&e2[iB]);
    }
}

__global__ void __launch_bounds__(256)
grid_encode_kernel(const float* __restrict__ in,
                   const float2* __restrict__ emb,
                   const float4* __restrict__ emb4,
                   float2* __restrict__ out,
                   int B)
{
    int t = blockIdx.x * blockDim.x + threadIdx.x;
    int p = t >> 4;           // point index
    int l = t & 15;           // level index
    if (p >= B) return;

    // map inputs from [-1,1] to [0,1]
    float x = (in[p * 3 + 0] + 1.0f) * 0.5f;
    float y = (in[p * 3 + 1] + 1.0f) * 0.5f;
    float z = (in[p * 3 + 2] + 1.0f) * 0.5f;

    float scale = c_scale[l];
    float px = fmaf(x, scale, 0.5f);
    float py = fmaf(y, scale, 0.5f);
    float pz = fmaf(z, scale, 0.5f);

    float fx = floorf(px), fy = floorf(py), fz = floorf(pz);
    uint32_t gx = (uint32_t)fx, gy = (uint32_t)fy, gz = (uint32_t)fz;
    float rx = px - fx, ry = py - fy, rz = pz - fz;

    uint32_t off = c_off[l];

    // Corner indices: pairs along x for the 4 (y,z) combos.
    uint32_t i00a, i00b, i10a, i10b, i01a, i01b, i11a, i11b;
    if (l >= 3) {
        uint32_t x0 = gx,              x1 = gx + 1u;
        uint32_t y0 = gy * PRIME1,     y1 = (gy + 1u) * PRIME1;
        uint32_t z0 = gz * PRIME2,     z1 = (gz + 1u) * PRIME2;
        uint32_t h00 = y0 ^ z0, h10 = y1 ^ z0, h01 = y0 ^ z1, h11 = y1 ^ z1;
        i00a = ((x0 ^ h00) & HASH_MASK) + off;
        i00b = ((x1 ^ h00) & HASH_MASK) + off;
        i10a = ((x0 ^ h10) & HASH_MASK) + off;
        i10b = ((x1 ^ h10) & HASH_MASK) + off;
        i01a = ((x0 ^ h01) & HASH_MASK) + off;
        i01b = ((x1 ^ h01) & HASH_MASK) + off;
        i11a = ((x0 ^ h11) & HASH_MASK) + off;
        i11b = ((x1 ^ h11) & HASH_MASK) + off;
    } else {
        uint32_t base = c_base[l];
        uint32_t b2 = base * base;
        uint32_t y0 = gy * base, y1 = y0 + base;
        uint32_t z0 = gz * b2,   z1 = z0 + b2;
        uint32_t s00 = y0 + z0 + off, s10 = y1 + z0 + off;
        uint32_t s01 = y0 + z1 + off, s11 = y1 + z1 + off;
        i00a = gx + s00; i00b = i00a + 1u;
        i10a = gx + s10; i10b = i10a + 1u;
        i01a = gx + s01; i01b = i01a + 1u;
        i11a = gx + s11; i11b = i11a + 1u;
    }

    float2 e0, e1, e2c, e3, e4c, e5, e6, e7;
    load_pair(emb, emb4, i00a, i00b, e0,  e1);
    load_pair(emb, emb4, i10a, i10b, e2c, e3);
    load_pair(emb, emb4, i01a, i01b, e4c, e5);
    load_pair(emb, emb4, i11a, i11b, e6,  e7);

    float wx0 = 1.0f - rx, wx1 = rx;
    float wy0 = 1.0f - ry, wy1 = ry;
    float wz0 = 1.0f - rz, wz1 = rz;

    float w00 = wy0 * wz0, w10 = wy1 * wz0, w01 = wy0 * wz1, w11 = wy1 * wz1;

    float w0 = wx0 * w00, w1 = wx1 * w00;
    float w2 = wx0 * w10, w3 = wx1 * w10;
    float w4 = wx0 * w01, w5 = wx1 * w01;
    float w6 = wx0 * w11, w7 = wx1 * w11;

    float a0 = w0 * e0.x;            float a1 = w0 * e0.y;
    a0 = fmaf(w1, e1.x,  a0);        a1 = fmaf(w1, e1.y,  a1);
    a0 = fmaf(w2, e2c.x, a0);        a1 = fmaf(w2, e2c.y, a1);
    a0 = fmaf(w3, e3.x,  a0);        a1 = fmaf(w3, e3.y,  a1);
    a0 = fmaf(w4, e4c.x, a0);        a1 = fmaf(w4, e4c.y, a1);
    a0 = fmaf(w5, e5.x,  a0);        a1 = fmaf(w5, e5.y,  a1);
    a0 = fmaf(w6, e6.x,  a0);        a1 = fmaf(w6, e6.y,  a1);
    a0 = fmaf(w7, e7.x,  a0);        a1 = fmaf(w7, e7.y,  a1);

    out[p * 16 + l] = make_float2(a0, a1);
}

extern "C" void kernel_launch(void* const* d_in, const int* in_sizes, int n_in,
                              void* d_out, int out_size) {
    const float*  inputs = (const float*)d_in[0];       // [B, 3]
    const float2* emb    = (const float2*)d_in[1];      // [TOTAL_PARAMS, 2]
    const float4* emb4   = (const float4*)d_in[1];      // same buffer, 16B view
    float2*       out    = (float2*)d_out;              // [B, 16] of float2

    int B = in_sizes[0] / 3;
    int threads = 256;
    long long total = (long long)B * 16;
    int blocks = (int)((total + threads - 1) / threads);
    grid_encode_kernel<<<blocks, threads>>>(inputs, emb, emb4, out, B);
}

// round 3
// speedup vs baseline: 1.2130x; 1.0450x over previous
#include <cuda_runtime.h>
#include <cuda_fp16.h>
#include <cstdint>

// GridEncoder (instant-ngp style), D=3, L=16, C=2, H=16, PLS=2, log2_hashmap=19,
// align_corners=false.
//
// R3: per-call fp32->half2 table conversion into __device__ scratch, then
// quad-fused gathers: x-pair indices satisfy idB = idA ^ (2^m - 1); with 4B
// half2 entries, m<=2 (75%) fits one 16B LDG.128 -> 5 lane-loads/point-level.

#define NLEV 16
#define PRIME1 2654435761u
#define PRIME2 805459861u
#define HASH_MASK 0x7FFFFu
#define TOTAL_PARAMS 7131240

__device__ __align__(16) __half2 g_embh[TOTAL_PARAMS];   // 28.5 MB scratch

__constant__ uint32_t c_off[NLEV] = {
    0u, 4920u, 40864u, 315496u,
    839784u, 1364072u, 1888360u, 2412648u,
    2936936u, 3461224u, 3985512u, 4509800u,
    5034088u, 5558376u, 6082664u, 6606952u
};
__constant__ float c_scale[NLEV] = {
    15.f, 31.f, 63.f, 127.f, 255.f, 511.f, 1023.f, 2047.f,
    4095.f, 8191.f, 16383.f, 32767.f, 65535.f, 131071.f, 262143.f, 524287.f
};
__constant__ uint32_t c_base[3] = {17u, 33u, 65u};

// fp32 [N,2] -> half2 [N], 2 entries per thread (float4 reads)
__global__ void __launch_bounds__(256)
convert_kernel(const float4* __restrict__ emb, int npairs)
{
    int i = blockIdx.x * blockDim.x + threadIdx.x;
    if (i < npairs) {
        float4 v = __ldg(&emb[i]);
        g_embh[2 * i + 0] = __floats2half2_rn(v.x, v.y);
        g_embh[2 * i + 1] = __floats2half2_rn(v.z, v.w);
    }
}

__device__ __forceinline__ uint32_t pick4(uint4 q, uint32_t k)
{
    uint32_t lo = (k & 1u) ? q.y : q.x;
    uint32_t hi = (k & 1u) ? q.w : q.z;
    return (k & 2u) ? hi : lo;
}

__device__ __forceinline__ float2 h2f(uint32_t h)
{
    __half2 v = *reinterpret_cast<__half2*>(&h);
    return __half22float2(v);
}

// Load embeddings for an x-adjacent corner pair.
__device__ __forceinline__ void load_pair(uint32_t iA, uint32_t iB,
                                          float2& ea, float2& eb)
{
    uint32_t diff = iA ^ iB;
    if (diff < 4u) {
        // both entries in the same 16B-aligned quad of half2s
        const uint4* qp = reinterpret_cast<const uint4*>(g_embh + (iA & ~3u));
        uint4 q = __ldg(qp);
        ea = h2f(pick4(q, iA & 3u));
        eb = h2f(pick4(q, iB & 3u));
    } else {
        ea = h2f(__ldg(reinterpret_cast<const uint32_t*>(g_embh + iA)));
        eb = h2f(__ldg(reinterpret_cast<const uint32_t*>(g_embh + iB)));
    }
}

__global__ void __launch_bounds__(256)
grid_encode_kernel(const float* __restrict__ in,
                   float2* __restrict__ out,
                   int B)
{
    int t = blockIdx.x * blockDim.x + threadIdx.x;
    int p = t >> 4;           // point index
    int l = t & 15;           // level index
    if (p >= B) return;

    // map inputs from [-1,1] to [0,1]
    float x = (in[p * 3 + 0] + 1.0f) * 0.5f;
    float y = (in[p * 3 + 1] + 1.0f) * 0.5f;
    float z = (in[p * 3 + 2] + 1.0f) * 0.5f;

    float scale = c_scale[l];
    float px = fmaf(x, scale, 0.5f);
    float py = fmaf(y, scale, 0.5f);
    float pz = fmaf(z, scale, 0.5f);

    float fx = floorf(px), fy = floorf(py), fz = floorf(pz);
    uint32_t gx = (uint32_t)fx, gy = (uint32_t)fy, gz = (uint32_t)fz;
    float rx = px - fx, ry = py - fy, rz = pz - fz;

    uint32_t off = c_off[l];

    uint32_t i00a, i00b, i10a, i10b, i01a, i01b, i11a, i11b;
    if (l >= 3) {
        uint32_t x0 = gx,              x1 = gx + 1u;
        uint32_t y0 = gy * PRIME1,     y1 = (gy + 1u) * PRIME1;
        uint32_t z0 = gz * PRIME2,     z1 = (gz + 1u) * PRIME2;
        uint32_t h00 = y0 ^ z0, h10 = y1 ^ z0, h01 = y0 ^ z1, h11 = y1 ^ z1;
        i00a = ((x0 ^ h00) & HASH_MASK) + off;
        i00b = ((x1 ^ h00) & HASH_MASK) + off;
        i10a = ((x0 ^ h10) & HASH_MASK) + off;
        i10b = ((x1 ^ h10) & HASH_MASK) + off;
        i01a = ((x0 ^ h01) & HASH_MASK) + off;
        i01b = ((x1 ^ h01) & HASH_MASK) + off;
        i11a = ((x0 ^ h11) & HASH_MASK) + off;
        i11b = ((x1 ^ h11) & HASH_MASK) + off;
    } else {
        uint32_t base = c_base[l];
        uint32_t b2 = base * base;
        uint32_t y0 = gy * base, y1 = y0 + base;
        uint32_t z0 = gz * b2,   z1 = z0 + b2;
        uint32_t s00 = y0 + z0 + off, s10 = y1 + z0 + off;
        uint32_t s01 = y0 + z1 + off, s11 = y1 + z1 + off;
        i00a = gx + s00; i00b = i00a + 1u;
        i10a = gx + s10; i10b = i10a + 1u;
        i01a = gx + s01; i01b = i01a + 1u;
        i11a = gx + s11; i11b = i11a + 1u;
    }

    float2 e0, e1, e2c, e3, e4c, e5, e6, e7;
    load_pair(i00a, i00b, e0,  e1);
    load_pair(i10a, i10b, e2c, e3);
    load_pair(i01a, i01b, e4c, e5);
    load_pair(i11a, i11b, e6,  e7);

    float wx0 = 1.0f - rx, wx1 = rx;
    float wy0 = 1.0f - ry, wy1 = ry;
    float wz0 = 1.0f - rz, wz1 = rz;

    float w00 = wy0 * wz0, w10 = wy1 * wz0, w01 = wy0 * wz1, w11 = wy1 * wz1;

    float w0 = wx0 * w00, w1 = wx1 * w00;
    float w2 = wx0 * w10, w3 = wx1 * w10;
    float w4 = wx0 * w01, w5 = wx1 * w01;
    float w6 = wx0 * w11, w7 = wx1 * w11;

    float a0 = w0 * e0.x;            float a1 = w0 * e0.y;
    a0 = fmaf(w1, e1.x,  a0);        a1 = fmaf(w1, e1.y,  a1);
    a0 = fmaf(w2, e2c.x, a0);        a1 = fmaf(w2, e2c.y, a1);
    a0 = fmaf(w3, e3.x,  a0);        a1 = fmaf(w3, e3.y,  a1);
    a0 = fmaf(w4, e4c.x, a0);        a1 = fmaf(w4, e4c.y, a1);
    a0 = fmaf(w5, e5.x,  a0);        a1 = fmaf(w5, e5.y,  a1);
    a0 = fmaf(w6, e6.x,  a0);        a1 = fmaf(w6, e6.y,  a1);
    a0 = fmaf(w7, e7.x,  a0);        a1 = fmaf(w7, e7.y,  a1);

    out[p * 16 + l] = make_float2(a0, a1);
}

extern "C" void kernel_launch(void* const* d_in, const int* in_sizes, int n_in,
                              void* d_out, int out_size) {
    const float*  inputs = (const float*)d_in[0];       // [B, 3]
    const float4* emb4   = (const float4*)d_in[1];      // [N,2] fp32 as pairs-of-rows
    float2*       out    = (float2*)d_out;              // [B, 16] of float2

    int B = in_sizes[0] / 3;

    // 1) convert table fp32 -> half2 (TOTAL_PARAMS is even)
    int npairs = TOTAL_PARAMS / 2;
    convert_kernel<<<(npairs + 255) / 256, 256>>>(emb4, npairs);

    // 2) main encode
    int threads = 256;
    long long total = (long long)B * 16;
    int blocks = (int)((total + threads - 1) / threads);
    grid_encode_kernel<<<blocks, threads>>>(inputs, out, B);
}